// round 10
// baseline (speedup 1.0000x reference)
#include <cuda_runtime.h>

#define BB 16
#define CC 32
#define TPB 128
#define MAXBLK 2048

// Scratch (no device allocations). g_bar self-resets -> graph-replay safe.
__device__ double g_partials[MAXBLK];
__device__ unsigned int g_bar = 0;

__device__ __forceinline__ float fast_ex2(float x) {
    float r; asm("ex2.approx.ftz.f32 %0, %1;" : "=f"(r) : "f"(x)); return r;
}
__device__ __forceinline__ float fast_lg2(float x) {
    float r; asm("lg2.approx.ftz.f32 %0, %1;" : "=f"(r) : "f"(x)); return r;
}

// Quarter-split: 4 lanes {k, k+8, k+16, k+24} form a quad handling one n.
// Quarter q = lane>>3 owns classes 8q..8q+7. All math fp32. Register-dieted
// to fit 12 blocks/SM (48 warps) for load/MUFU overlap.
template <int NC>
__global__ void __launch_bounds__(TPB, 12) fpce_fused(const float* __restrict__ pred,
                                                      const int* __restrict__ tru,
                                                      int Nrt,
                                                      float* __restrict__ out) {
    const int N = (NC > 0) ? NC : Nrt;
    const float LOG2E = 1.4426950408889634f;

    const int tid  = threadIdx.x;
    const int lane = tid & 31;
    const int warp = tid >> 5;
    const int q    = lane >> 3;          // class quarter (0..3)
    const int k    = lane & 7;           // n slot within warp
    const int NPB  = (TPB / 32) * 8;     // 32 n per block-iteration

    float thread_total = 0.0f;

    for (int n0 = blockIdx.x * NPB; n0 < N; n0 += gridDim.x * NPB) {
        int n = n0 + warp * 8 + k;
        const bool valid = (n < N);
        if (!valid) n = N - 1;           // clamp: whole quad clamps identically

        // ---- Counts for MY 8 classes: 8-bit fields in one u64.
        unsigned long long pc = 0ull;
#pragma unroll
        for (int b = 0; b < BB; b++) {
            const int t  = tru[b * N + n];        // quad lanes read same addr (coalesces)
            const int lt = t - q * 8;
            pc += ((unsigned)lt < 8u) ? (1ull << (8 * (lt & 7))) : 0ull;
        }
        if (!valid) pc = 0ull;                    // zero weight -> zero contribution
        float cntf[8];
#pragma unroll
        for (int j = 0; j < 8; j++)
            cntf[j] = (float)((unsigned)(pc >> (8 * j)) & 0xFFu);

        const float* rowbase = pred + (size_t)(q * 8) * (size_t)N + (size_t)n;
        const size_t bstride = (size_t)CC * (size_t)N;

        // Prime buffer (b = 0).
        float xa[8];
#pragma unroll
        for (int j = 0; j < 8; j++) xa[j] = rowbase[(size_t)j * (size_t)N];

#pragma unroll 1
        for (int b = 0; b < BB; b++) {
            float y[8];
#pragma unroll
            for (int j = 0; j < 8; j++) y[j] = xa[j] * LOG2E;

            // Prefetch next b-round while computing this one.
            if (b + 1 < BB) {
                const float* rb = rowbase + (size_t)(b + 1) * bstride;
#pragma unroll
                for (int j = 0; j < 8; j++) xa[j] = rb[(size_t)j * (size_t)N];
            }

            // Phase 1: partial Z over my 8 classes, 2 parallel chains.
            float s0 = 0.f, s1 = 0.f;
#pragma unroll
            for (int j = 0; j < 8; j++) {
                const float e = fast_ex2(y[j]);
                if (j & 1) s1 += e; else s0 += e;
            }
            float s = s0 + s1;
            // Quad allreduce across the 4 quarters.
            s += __shfl_xor_sync(0xffffffffu, s, 8);
            s += __shfl_xor_sync(0xffffffffu, s, 16);
            const float L2 = fast_lg2(s);         // log2 Z

            // Phase 2: f = d * 2^d, d = log2Z - y >= 0, weighted by counts.
            float a0 = 0.f, a1 = 0.f;
#pragma unroll
            for (int j = 0; j < 8; j++) {
                const float d = L2 - y[j];
                const float e = fast_ex2(d);
                const float t = cntf[j] * d;
                if (j & 1) a1 = fmaf(t, e, a1); else a0 = fmaf(t, e, a0);
            }
            thread_total += a0 + a1;
        }
    }
    thread_total *= 0.6931471805599453f;  // ln2 once (log2 -> ln domain)

    // ---- Block reduction (double).
    double v = (double)thread_total;
#pragma unroll
    for (int off = 16; off > 0; off >>= 1)
        v += __shfl_down_sync(0xffffffffu, v, off);

    __shared__ double wsum[TPB / 32];
    const int wid = threadIdx.x >> 5;
    if ((threadIdx.x & 31) == 0) wsum[wid] = v;
    __syncthreads();

    __shared__ int isLast;
    if (threadIdx.x == 0) {
        double bsum = 0.0;
#pragma unroll
        for (int w = 0; w < TPB / 32; w++) bsum += wsum[w];
        g_partials[blockIdx.x] = bsum;
        __threadfence();
        const unsigned done = atomicAdd(&g_bar, 1u);
        isLast = (done == gridDim.x - 1) ? 1 : 0;
    }
    __syncthreads();

    if (isLast) {
        double t = 0.0;
        for (int i = threadIdx.x; i < (int)gridDim.x; i += TPB) t += g_partials[i];
#pragma unroll
        for (int off = 16; off > 0; off >>= 1)
            t += __shfl_down_sync(0xffffffffu, t, off);
        if ((threadIdx.x & 31) == 0) wsum[wid] = t;
        __syncthreads();
        if (threadIdx.x == 0) {
            double total = 0.0;
#pragma unroll
            for (int w = 0; w < TPB / 32; w++) total += wsum[w];
            out[0] = (float)(total / (double)N);
            atomicExch(&g_bar, 0u);   // reset for next graph replay
        }
    }
}

extern "C" void kernel_launch(void* const* d_in, const int* in_sizes, int n_in,
                              void* d_out, int out_size) {
    const float* pred = (const float*)d_in[0];
    const int*   tru  = (const int*)d_in[1];
    float*       out  = (float*)d_out;

    const int N = in_sizes[1] / BB;  // true is (B, N)

    const int npb = (TPB / 32) * 8;          // 32 n per block-iteration
    int nb = (N + npb - 1) / npb;
    int blocks = 148 * 12;                    // exactly one resident wave
    if (blocks > nb) blocks = nb;
    if (blocks > MAXBLK) blocks = MAXBLK;

    if (N == 131072) {
        fpce_fused<131072><<<blocks, TPB>>>(pred, tru, N, out);
    } else {
        fpce_fused<0><<<blocks, TPB>>>(pred, tru, N, out);
    }
}